// round 14
// baseline (speedup 1.0000x reference)
#include <cuda_runtime.h>
#include <cuda_bf16.h>
#include <math.h>

#define NN 50000
#define NE 800000
#define NG 256
#define HID 128
#define BN_EPS 1e-5f
#define NBLK 49   // ceil(NN/1024)

// ---------------- persistent scratch (device globals; no allocations) ----------------
// Invariant: g_deg is all-zero at kernel_launch entry (k_scan re-zeroes it each call).
__device__ int   g_deg[NN];
__device__ int   g_fill[NN];
__device__ int   g_rowptr[NN + 1];
__device__ int   g_bsum[NBLK];
__device__ unsigned g_tick;         // monotonic ticket counter for k_scan barrier
__device__ int   g_src[NE];
__device__ float g_invdeg[NN];
__device__ __nv_bfloat16 g_xb[(size_t)NN * 64];     // x in bf16
__device__ __nv_bfloat16 g_wb[6 * 16384];           // weights bf16, [n][k], slot-stride 16384
__device__ __nv_bfloat16 g_hpa[(size_t)NN * HID];   // pre-BN activations ping
__device__ __nv_bfloat16 g_hpb[(size_t)NN * HID];   // pre-BN activations pong
__device__ float g_colsum[3][HID];
__device__ float g_colsumsq[3][HID];

__device__ __forceinline__ int clampi(int v, int hi) { return min(max(v, 0), hi); }

__device__ __forceinline__ void mma_bf16(float c[4], const unsigned a[4], const unsigned b[2]) {
    asm volatile(
        "mma.sync.aligned.m16n8k16.row.col.f32.bf16.bf16.f32 "
        "{%0,%1,%2,%3}, {%4,%5,%6,%7}, {%8,%9}, {%0,%1,%2,%3};"
        : "+f"(c[0]), "+f"(c[1]), "+f"(c[2]), "+f"(c[3])
        : "r"(a[0]), "r"(a[1]), "r"(a[2]), "r"(a[3]), "r"(b[0]), "r"(b[1]));
}

// Blackwell packed f32x2 helpers
__device__ __forceinline__ void add2(float2& a, float2 b) {
    asm("add.rn.f32x2 %0, %1, %2;"
        : "=l"(*(unsigned long long*)&a)
        : "l"(*(unsigned long long*)&a), "l"(*(unsigned long long*)&b));
}
__device__ __forceinline__ float2 fma2(float2 s, float2 v, float2 t) {
    float2 r;
    asm("fma.rn.f32x2 %0, %1, %2, %3;"
        : "=l"(*(unsigned long long*)&r)
        : "l"(*(unsigned long long*)&s), "l"(*(unsigned long long*)&v),
          "l"(*(unsigned long long*)&t));
    return r;
}
__device__ __forceinline__ float2 cvt2(unsigned u) {
    return __bfloat1622float2(*(__nv_bfloat162*)&u);
}

__device__ __forceinline__ void cp16(unsigned dst, const void* src, int sz) {
    asm volatile("cp.async.cg.shared.global [%0], [%1], 16, %2;"
                 :: "r"(dst), "l"(src), "r"(sz));
}
#define CP_COMMIT() asm volatile("cp.async.commit_group;")
#define CP_WAIT0()  asm volatile("cp.async.wait_group 0;" ::: "memory")

// buffer codes: 0=xb, 1=hpa, 2=hpb
__device__ __forceinline__ const __nv_bfloat16* srcbuf(int B) {
    return B == 0 ? g_xb : (B == 1 ? g_hpa : g_hpb);
}
__device__ __forceinline__ __nv_bfloat16* dstbuf(int B) { return B == 1 ? g_hpa : g_hpb; }

// ---- prep: degree RED-atomics (4 edges/thread) + x->bf16 + weight transpose/convert ----
__global__ void k_prep(const float* __restrict__ x, const int* __restrict__ ei,
                       const float* __restrict__ Wn0, const float* __restrict__ Wr0,
                       const float* __restrict__ Wn1, const float* __restrict__ Wr1,
                       const float* __restrict__ Wn2, const float* __restrict__ Wr2) {
    int i = blockIdx.x * blockDim.x + threadIdx.x;   // 800000 threads
    if (i < NE / 4) {
        int4 d4 = *(const int4*)(ei + NE + i * 4);   // 4 dst indices, coalesced
        atomicAdd(&g_deg[clampi(d4.x, NN - 1)], 1);  // no-return -> RED, fire-and-forget
        atomicAdd(&g_deg[clampi(d4.y, NN - 1)], 1);
        atomicAdd(&g_deg[clampi(d4.z, NN - 1)], 1);
        atomicAdd(&g_deg[clampi(d4.w, NN - 1)], 1);
    }
    if (i < NN * 16) {
        float4 v = ((const float4*)x)[i];
        __nv_bfloat162 lo = __float22bfloat162_rn(make_float2(v.x, v.y));
        __nv_bfloat162 hi = __float22bfloat162_rn(make_float2(v.z, v.w));
        uint2 o;
        o.x = *(unsigned*)&lo;
        o.y = *(unsigned*)&hi;
        ((uint2*)g_xb)[i] = o;
    }
    if (i < 6 * 16384) {
        const float* Wp[6] = {Wn0, Wr0, Wn1, Wr1, Wn2, Wr2};
        int slot = i >> 14;
        int rem = i & 16383;
        int K = slot < 2 ? 64 : 128;
        if (rem < 128 * K) {
            int n = rem % 128;
            int k = rem / 128;
            g_wb[slot * 16384 + n * K + k] = __float2bfloat16_rn(Wp[slot][k * 128 + n]);
        }
    }
}

// ---- merged scan: block sums -> ticket barrier -> rowptr/invdeg; seeds fill; zeros deg ----
__global__ void k_scan() {
    int b = blockIdx.x;                 // NBLK blocks x 1024
    int t = threadIdx.x;
    int i = b * 1024 + t;
    if (b == 0 && t < 384) { ((float*)g_colsum)[t] = 0.0f; ((float*)g_colsumsq)[t] = 0.0f; }
    __shared__ int sc[1024];
    int d = (i < NN) ? g_deg[i] : 0;
    sc[t] = d;
    __syncthreads();
    for (int off = 1; off < 1024; off <<= 1) {      // inclusive Hillis-Steele
        int v = (t >= off) ? sc[t - off] : 0;
        __syncthreads();
        sc[t] += v;
        __syncthreads();
    }
    if (t == 1023) {
        g_bsum[b] = sc[1023];
        __threadfence();
    }
    __syncthreads();
    // grid barrier: monotonic ticket (never reset; safe across graph replays)
    if (t == 0) {
        unsigned my = atomicAdd(&g_tick, 1u) + 1u;
        unsigned target = ((my + NBLK - 1u) / NBLK) * NBLK;
        while (*(volatile unsigned*)&g_tick < target) { }
        __threadfence();
    }
    __syncthreads();
    int base = 0;
    for (int j = 0; j < b; j++) base += *(volatile int*)&g_bsum[j];
    int excl = base + sc[t] - d;
    if (i < NN) {
        g_rowptr[i] = excl;
        g_fill[i] = excl;
        g_invdeg[i] = 1.0f / fmaxf((float)d, 1.0f);
        g_deg[i] = 0;
        if (i == NN - 1) g_rowptr[NN] = excl + d;
    }
}

// ---- CSR fill: 4 edges/thread, 4 returning atomics in flight ----
__global__ void k_fill(const int* __restrict__ ei) {
    int i = blockIdx.x * blockDim.x + threadIdx.x;
    if (i >= NE / 4) return;
    int4 d4 = *(const int4*)(ei + NE + i * 4);
    int4 s4 = *(const int4*)(ei + i * 4);
    int p0 = atomicAdd(&g_fill[clampi(d4.x, NN - 1)], 1);
    int p1 = atomicAdd(&g_fill[clampi(d4.y, NN - 1)], 1);
    int p2 = atomicAdd(&g_fill[clampi(d4.z, NN - 1)], 1);
    int p3 = atomicAdd(&g_fill[clampi(d4.w, NN - 1)], 1);
    if (p0 < NE) g_src[p0] = clampi(s4.x, NN - 1);
    if (p1 < NE) g_src[p1] = clampi(s4.y, NN - 1);
    if (p2 < NE) g_src[p2] = clampi(s4.z, NN - 1);
    if (p3 < NE) g_src[p3] = clampi(s4.w, NN - 1);
}

// ==== fused layer: aggregate (Phase A, into smem) + dual GEMM (Phase B) + BN-stats ====
// Phase A: Af[rr][:] = inv_deg * sum_e act(in[src[e]][:]);  Cf[rr][:] = act(in[row][:])
//          act = BN? relu(s*v+t) : v   (BN consts from previous layer's stats)
// Phase B: dst = bf16(Af@W1 + Cf@W2), weights streamed via cp.async double buffer.
// BM=64 rows/block, BN=128; 8 warps (2M x 4N), warp tile 32x32, mma m16n8k16.
template <int K, int SRCB, int DSTB, bool BN>
__global__ void __launch_bounds__(256, 2)
k_layer(int slot1, int slot2, int layer,
        const float* __restrict__ gammaP, const float* __restrict__ betaP, int statP) {
    const int NV = K / 64;              // uint4 per lane per row
    const int ROW = K / 8;              // uint4 per row
    const int RS = K + 8;               // smem row stride (bf16)
    const int S = K / 16;               // k-steps per segment
    const int T = 2 * S;

    __shared__ __nv_bfloat16 Af[64 * (K + 8)];
    __shared__ __nv_bfloat16 Cf[64 * (K + 8)];
    __shared__ __nv_bfloat16 Wd[2][128 * 24];

    int tid = threadIdx.x;
    int lane = tid & 31;
    int wid = tid >> 5;
    int warp_m = wid & 1;
    int warp_n = wid >> 1;
    int g = lane >> 2;
    int tg = lane & 3;
    int blockRow = blockIdx.x * 64;

    // ---- weight streaming setup; kick off step 0 before Phase A ----
    int wr = tid >> 1;
    int whalf = tid & 1;
    const __nv_bfloat16* W1 = g_wb + slot1 * 16384;
    const __nv_bfloat16* W2 = g_wb + slot2 * 16384;
    unsigned wdBase = (unsigned)__cvta_generic_to_shared(&Wd[0][0]);
    unsigned tileOffW = ((unsigned)(wr * 24 + whalf * 8)) * 2;
    const unsigned BUFW = 128 * 24 * 2;
    auto issue = [&](int step) {
        const __nv_bfloat16* Wp = (step >= S) ? W2 : W1;
        int k0 = (step - (step >= S ? S : 0)) * 16;
        cp16(wdBase + (unsigned)(step & 1) * BUFW + tileOffW, Wp + wr * K + k0 + whalf * 8, 16);
        CP_COMMIT();
    };
    issue(0);

    // ---- Phase A: aggregate own 64 rows into Af; act rows into Cf ----
    {
        const uint4* __restrict__ in4 = (const uint4*)srcbuf(SRCB);
        int f = tid & 7;
        int base = f * NV;

        float2 s2[NV][4], t2[NV][4];
        if (BN) {
            const float invN = 1.0f / (float)NN;
#pragma unroll
            for (int v = 0; v < NV; v++) {
                int c0 = (base + v) * 8;
#pragma unroll
                for (int j = 0; j < 4; j++) {
                    float2 sv, tv;
#pragma unroll
                    for (int q = 0; q < 2; q++) {
                        int c = c0 + 2 * j + q;
                        float mu = g_colsum[statP][c] * invN;
                        float var = g_colsumsq[statP][c] * invN - mu * mu;
                        float sc = gammaP[c] * rsqrtf(var + BN_EPS);
                        (q ? sv.y : sv.x) = sc;
                        (q ? tv.y : tv.x) = betaP[c] - mu * sc;
                    }
                    s2[v][j] = sv;
                    t2[v][j] = tv;
                }
            }
        }

#pragma unroll
        for (int q = 0; q < 2; q++) {
            int rr = (tid >> 3) + 32 * q;
            int gr = blockRow + rr;
            if (gr < NN) {
                float2 acc[NV][4];
#pragma unroll
                for (int v = 0; v < NV; v++)
#pragma unroll
                    for (int j = 0; j < 4; j++) acc[v][j] = make_float2(0.f, 0.f);

                auto lanefn = [&](int v, uint4 u) {
                    unsigned w[4] = {u.x, u.y, u.z, u.w};
#pragma unroll
                    for (int j = 0; j < 4; j++) {
                        float2 p = cvt2(w[j]);
                        if (BN) {
                            p = fma2(s2[v][j], p, t2[v][j]);
                            p.x = fmaxf(p.x, 0.0f);
                            p.y = fmaxf(p.y, 0.0f);
                        }
                        add2(acc[v][j], p);
                    }
                };

                int s = g_rowptr[gr], e = g_rowptr[gr + 1];
                int i = s;
                for (; i + 1 < e; i += 2) {
                    int a0 = g_src[i] * ROW + base;
                    int a1 = g_src[i + 1] * ROW + base;
                    uint4 u0[NV], u1[NV];
#pragma unroll
                    for (int v = 0; v < NV; v++) u0[v] = in4[a0 + v];
#pragma unroll
                    for (int v = 0; v < NV; v++) u1[v] = in4[a1 + v];
#pragma unroll
                    for (int v = 0; v < NV; v++) { lanefn(v, u0[v]); lanefn(v, u1[v]); }
                }
                if (i < e) {
                    int a0 = g_src[i] * ROW + base;
#pragma unroll
                    for (int v = 0; v < NV; v++) lanefn(v, in4[a0 + v]);
                }

                float id = g_invdeg[gr];
#pragma unroll
                for (int v = 0; v < NV; v++) {
                    uint4 o;
                    unsigned* ow = (unsigned*)&o;
#pragma unroll
                    for (int j = 0; j < 4; j++) {
                        __nv_bfloat162 b = __float22bfloat162_rn(
                            make_float2(acc[v][j].x * id, acc[v][j].y * id));
                        ow[j] = *(unsigned*)&b;
                    }
                    *(uint4*)&Af[rr * RS + (base + v) * 8] = o;
                }
                // act (A2 operand) for own row
#pragma unroll
                for (int v = 0; v < NV; v++) {
                    uint4 u = in4[gr * ROW + base + v];
                    if (BN) {
                        unsigned* w = (unsigned*)&u;
#pragma unroll
                        for (int j = 0; j < 4; j++) {
                            float2 p = fma2(s2[v][j], cvt2(w[j]), t2[v][j]);
                            p.x = fmaxf(p.x, 0.0f);
                            p.y = fmaxf(p.y, 0.0f);
                            __nv_bfloat162 b = __float22bfloat162_rn(p);
                            w[j] = *(unsigned*)&b;
                        }
                    }
                    *(uint4*)&Cf[rr * RS + (base + v) * 8] = u;
                }
            } else {
                uint4 z = make_uint4(0u, 0u, 0u, 0u);
#pragma unroll
                for (int v = 0; v < NV; v++) {
                    *(uint4*)&Af[rr * RS + (base + v) * 8] = z;
                    *(uint4*)&Cf[rr * RS + (base + v) * 8] = z;
                }
            }
        }
    }

    // ---- Phase B: dual GEMM from resident Af/Cf, W double-buffered ----
    float acc[2][4][4];
#pragma unroll
    for (int mt = 0; mt < 2; mt++)
#pragma unroll
        for (int nt = 0; nt < 4; nt++)
#pragma unroll
            for (int q = 0; q < 4; q++) acc[mt][nt][q] = 0.0f;

#pragma unroll 1
    for (int s = 0; s < T; s++) {
        int cur = s & 1;
        CP_WAIT0();
        __syncthreads();                 // first iter also publishes Af/Cf
        if (s + 1 < T) issue(s + 1);
        const __nv_bfloat16* Asrc = (s >= S) ? Cf : Af;
        int k0 = (s - (s >= S ? S : 0)) * 16;
        unsigned a[2][4], b[4][2];
#pragma unroll
        for (int mt = 0; mt < 2; mt++) {
            int rr = warp_m * 32 + mt * 16 + g;
            a[mt][0] = *(const unsigned*)&Asrc[rr * RS + k0 + 2 * tg];
            a[mt][1] = *(const unsigned*)&Asrc[(rr + 8) * RS + k0 + 2 * tg];
            a[mt][2] = *(const unsigned*)&Asrc[rr * RS + k0 + 2 * tg + 8];
            a[mt][3] = *(const unsigned*)&Asrc[(rr + 8) * RS + k0 + 2 * tg + 8];
        }
#pragma unroll
        for (int nt = 0; nt < 4; nt++) {
            int c = warp_n * 32 + nt * 8 + g;
            b[nt][0] = *(const unsigned*)&Wd[cur][c * 24 + 2 * tg];
            b[nt][1] = *(const unsigned*)&Wd[cur][c * 24 + 2 * tg + 8];
        }
#pragma unroll
        for (int mt = 0; mt < 2; mt++)
#pragma unroll
            for (int nt = 0; nt < 4; nt++)
                mma_bf16(acc[mt][nt], a[mt], b[nt]);
        __syncthreads();                 // Wd[cur] fully consumed before refill
    }

    // ---- epilogue: store acc -> dst (bf16), fused per-column sum/sumsq ----
    __nv_bfloat16* dst = dstbuf(DSTB);
#pragma unroll
    for (int mt = 0; mt < 2; mt++) {
        int r0 = blockRow + warp_m * 32 + mt * 16 + g;
#pragma unroll
        for (int nt = 0; nt < 4; nt++) {
            int c = warp_n * 32 + nt * 8 + 2 * tg;
            if (r0 < NN) {
                __nv_bfloat162 v = __float22bfloat162_rn(make_float2(acc[mt][nt][0], acc[mt][nt][1]));
                *(__nv_bfloat162*)(dst + r0 * 128 + c) = v;
            }
            if (r0 + 8 < NN) {
                __nv_bfloat162 v = __float22bfloat162_rn(make_float2(acc[mt][nt][2], acc[mt][nt][3]));
                *(__nv_bfloat162*)(dst + (r0 + 8) * 128 + c) = v;
            }
        }
    }
#pragma unroll
    for (int nt = 0; nt < 4; nt++) {
        float s0 = 0.f, s1 = 0.f, q0 = 0.f, q1 = 0.f;
#pragma unroll
        for (int mt = 0; mt < 2; mt++) {
            float a0 = acc[mt][nt][0], a1 = acc[mt][nt][1];
            float a2 = acc[mt][nt][2], a3 = acc[mt][nt][3];
            s0 += a0 + a2; s1 += a1 + a3;
            q0 += a0 * a0 + a2 * a2; q1 += a1 * a1 + a3 * a3;
        }
#pragma unroll
        for (int off = 4; off < 32; off <<= 1) {
            s0 += __shfl_xor_sync(0xffffffffu, s0, off);
            s1 += __shfl_xor_sync(0xffffffffu, s1, off);
            q0 += __shfl_xor_sync(0xffffffffu, q0, off);
            q1 += __shfl_xor_sync(0xffffffffu, q1, off);
        }
        if (lane < 4) {
            int c = warp_n * 32 + nt * 8 + 2 * tg;
            atomicAdd(&g_colsum[layer][c], s0);
            atomicAdd(&g_colsum[layer][c + 1], s1);
            atomicAdd(&g_colsumsq[layer][c], q0);
            atomicAdd(&g_colsumsq[layer][c + 1], q1);
        }
    }
}

// ---- fused segmented mean-pool (BN on-the-fly, binary-searched bounds) + MLP head ----
__global__ void k_poolmlp(const int* __restrict__ batch,
                          const float* __restrict__ gamma, const float* __restrict__ beta,
                          const float* __restrict__ fc1W, const float* __restrict__ fc1b,
                          const float* __restrict__ fc2W, const float* __restrict__ fc2b,
                          float* __restrict__ out) {
    int g = blockIdx.x;
    int t = threadIdx.x;
    __shared__ float p[128];
    __shared__ float zred[2];

    int lo = 0, hi = NN;
    while (lo < hi) { int m = (lo + hi) >> 1; if (batch[m] < g) lo = m + 1; else hi = m; }
    int start = lo;
    hi = NN;
    while (lo < hi) { int m = (lo + hi) >> 1; if (batch[m] < g + 1) lo = m + 1; else hi = m; }
    int end = lo;
    int cnt = end - start;

    const float invN = 1.0f / (float)NN;
    float mu = g_colsum[2][t] * invN;
    float var = g_colsumsq[2][t] * invN - mu * mu;
    float sc = gamma[t] * rsqrtf(var + BN_EPS);
    float tc = beta[t] - mu * sc;

    float acc = 0.0f;
    for (int r = start; r < end; r++) {
        float v = __bfloat162float(g_hpa[r * 128 + t]);
        acc += fmaxf(sc * v + tc, 0.0f);
    }
    p[t] = acc / (float)max(cnt, 1);
    __syncthreads();

    if (t < 64) {
        float z = fc1b[t];
#pragma unroll 8
        for (int k = 0; k < 128; k++) z += p[k] * fc1W[k * 64 + t];
        z = fmaxf(z, 0.0f) * fc2W[t];
#pragma unroll
        for (int off = 16; off; off >>= 1) z += __shfl_down_sync(0xffffffffu, z, off);
        if ((t & 31) == 0) zred[t >> 5] = z;
    }
    __syncthreads();
    if (t == 0) {
        float s = zred[0] + zred[1] + fc2b[0];
        out[g] = 1.0f / (1.0f + expf(-s));
    }
}

// ---------------- host launcher: kernel launches ONLY ----------------
extern "C" void kernel_launch(void* const* d_in, const int* in_sizes, int n_in,
                              void* d_out, int out_size) {
    const float* x     = (const float*)d_in[0];
    const int*   ei    = (const int*)d_in[1];     // int64 narrowed to int32 by harness
    const int*   batch = (const int*)d_in[2];
    const float* Wn0 = (const float*)d_in[3];
    const float* Wr0 = (const float*)d_in[4];
    const float* Wn1 = (const float*)d_in[6];
    const float* Wr1 = (const float*)d_in[7];
    const float* Wn2 = (const float*)d_in[9];
    const float* Wr2 = (const float*)d_in[10];
    const float* gamma = (const float*)d_in[12]; // [3,128]
    const float* beta  = (const float*)d_in[13];
    const float* fc1W = (const float*)d_in[14];
    const float* fc1b = (const float*)d_in[15];
    const float* fc2W = (const float*)d_in[16];
    const float* fc2b = (const float*)d_in[17];
    float* out = (float*)d_out;

    // ---- setup: prep -> merged scan -> fill ----
    k_prep<<<(NN * 16 + 255) / 256, 256>>>(x, ei, Wn0, Wr0, Wn1, Wr1, Wn2, Wr2);
    k_scan<<<NBLK, 1024>>>();
    k_fill<<<(NE / 4 + 255) / 256, 256>>>(ei);

    const int layerGrid = (NN + 63) / 64;   // 782

    // ---- fused layers ----
    k_layer<64, 0, 1, false><<<layerGrid, 256>>>(0, 1, 0, nullptr, nullptr, 0);
    k_layer<128, 1, 2, true><<<layerGrid, 256>>>(2, 3, 1, gamma + 0 * HID, beta + 0 * HID, 0);
    k_layer<128, 2, 1, true><<<layerGrid, 256>>>(4, 5, 2, gamma + 1 * HID, beta + 1 * HID, 1);

    // ---- pool (BN(stats2) on-the-fly) + MLP head, fused ----
    k_poolmlp<<<NG, 128>>>(batch, gamma + 2 * HID, beta + 2 * HID, fc1W, fc1b, fc2W, fc2b, out);
}